// round 6
// baseline (speedup 1.0000x reference)
#include <cuda_runtime.h>
#include <math.h>
#include <stdint.h>

#define BATCH 4
#define NQ    2048
#define NR    16384
#define DIM   64
#define KNN   16

#define TQ 128
#define TR 128
#define QS (TQ + 4)
#define RS (TR + 4)

#define FULLM 0xffffffffu

// Scratch (allocation-free rule: __device__ globals)
__device__ float g_d2[(size_t)BATCH * NQ * NR];   // 512 MB
__device__ float g_r2[BATCH * NR];
__device__ float g_q2[BATCH * NQ];

// ---------------------------------------------------------------------------
// Kernel 1: squared norms, replicating XLA-GPU row-reduction order bit-exactly:
//   lane l: s = fl( fl(x_l^2) + fl(x_{l+32}^2) )        (mul-round, add-round)
//   then shfl_down tree: offsets 16, 8, 4, 2, 1.
// One warp per row.
// ---------------------------------------------------------------------------
__global__ void norms_kernel(const float* __restrict__ ref,
                             const float* __restrict__ query) {
    int warp = (blockIdx.x * blockDim.x + threadIdx.x) >> 5;
    int lane = threadIdx.x & 31;
    int total = BATCH * NR + BATCH * NQ;
    if (warp >= total) return;

    const float* row;
    float* out;
    if (warp < BATCH * NR) {
        row = ref + (size_t)warp * DIM;
        out = g_r2 + warp;
    } else {
        int u = warp - BATCH * NR;
        row = query + (size_t)u * DIM;
        out = g_q2 + u;
    }

    float x0 = row[lane];
    float x1 = row[lane + 32];
    float s = __fadd_rn(__fmul_rn(x0, x0), __fmul_rn(x1, x1));
#pragma unroll
    for (int off = 16; off; off >>= 1)
        s = __fadd_rn(s, __shfl_down_sync(FULLM, s, off));
    if (lane == 0) *out = s;
}

// ---------------------------------------------------------------------------
// Kernel 2: d2 = max( fl( fl(q2+r2) - 2*dot ), 0 ), dot = sequential ascending-k
// FMA chain (matches cublas/Eigen per-element accumulation). f32x2 packed FMAs
// round each half identically to scalar FFMA, and the chain is strictly
// k-ordered, so the dot is bit-equal to a scalar sequential FMA loop.
// Tile 128x128, K=64 resident, 256 threads, 8x8 micro-tile.
// ---------------------------------------------------------------------------
__global__ __launch_bounds__(256) void gemm_kernel(const float* __restrict__ ref,
                                                   const float* __restrict__ query) {
    extern __shared__ float sm[];
    float* Qs = sm;             // [DIM][QS]
    float* Rs = sm + DIM * QS;  // [DIM][RS]

    int b  = blockIdx.z;
    int q0 = blockIdx.y * TQ;
    int r0 = blockIdx.x * TR;
    int tid = threadIdx.x;

    const float* qg = query + ((size_t)b * NQ + q0) * DIM;
    const float* rg = ref   + ((size_t)b * NR + r0) * DIM;

    int frow = tid >> 4;
    int fd   = (tid & 15) * 4;
#pragma unroll
    for (int it = 0; it < 8; ++it) {
        int row = frow + it * 16;
        float4 v = *(const float4*)(qg + (size_t)row * DIM + fd);
        Qs[(fd + 0) * QS + row] = v.x;
        Qs[(fd + 1) * QS + row] = v.y;
        Qs[(fd + 2) * QS + row] = v.z;
        Qs[(fd + 3) * QS + row] = v.w;
        float4 w = *(const float4*)(rg + (size_t)row * DIM + fd);
        Rs[(fd + 0) * RS + row] = w.x;
        Rs[(fd + 1) * RS + row] = w.y;
        Rs[(fd + 2) * RS + row] = w.z;
        Rs[(fd + 3) * RS + row] = w.w;
    }
    __syncthreads();

    int qy = (tid >> 4) * 8;
    int rx = (tid & 15) * 8;

    unsigned long long acc[8][4];
#pragma unroll
    for (int i = 0; i < 8; i++)
#pragma unroll
        for (int j = 0; j < 4; j++) acc[i][j] = 0ull;

#pragma unroll 8
    for (int k = 0; k < DIM; k++) {
        float4 qa = *(const float4*)(Qs + k * QS + qy);
        float4 qb = *(const float4*)(Qs + k * QS + qy + 4);
        double2 ra = *(const double2*)(Rs + k * RS + rx);
        double2 rb = *(const double2*)(Rs + k * RS + rx + 4);
        unsigned long long r[4];
        r[0] = __double_as_longlong(ra.x);
        r[1] = __double_as_longlong(ra.y);
        r[2] = __double_as_longlong(rb.x);
        r[3] = __double_as_longlong(rb.y);
        float qv[8] = {qa.x, qa.y, qa.z, qa.w, qb.x, qb.y, qb.z, qb.w};
#pragma unroll
        for (int i = 0; i < 8; i++) {
            unsigned long long qd;
            unsigned qu = __float_as_uint(qv[i]);
            asm("mov.b64 %0, {%1, %1};" : "=l"(qd) : "r"(qu));
#pragma unroll
            for (int j = 0; j < 4; j++) {
                asm("fma.rn.f32x2 %0, %1, %2, %0;"
                    : "+l"(acc[i][j]) : "l"(qd), "l"(r[j]));
            }
        }
    }

    // Epilogue: d2 = max( fl( fl(q2 + r2) - 2*dot ), 0 )
    float r2v[8];
#pragma unroll
    for (int j = 0; j < 8; j++) r2v[j] = g_r2[b * NR + r0 + rx + j];

#pragma unroll
    for (int i = 0; i < 8; i++) {
        float q2v = g_q2[b * NQ + q0 + qy + i];
        float o[8];
#pragma unroll
        for (int j = 0; j < 4; j++) {
            unsigned long long a = acc[i][j];
            float lo = __uint_as_float((unsigned)(a & 0xffffffffull));
            float hi = __uint_as_float((unsigned)(a >> 32));
            float t0 = __fadd_rn(q2v, r2v[2 * j + 0]);
            float t1 = __fadd_rn(q2v, r2v[2 * j + 1]);
            // fmaf(-2, dot, t) rounds once == fl(t - fl(2*dot)) since 2*dot exact
            o[2 * j + 0] = fmaxf(__fmaf_rn(-2.f, lo, t0), 0.f);
            o[2 * j + 1] = fmaxf(__fmaf_rn(-2.f, hi, t1), 0.f);
        }
        float* dst = g_d2 + ((size_t)(b * NQ + q0 + qy + i)) * NR + r0 + rx;
        *(float4*)(dst + 0) = make_float4(o[0], o[1], o[2], o[3]);
        *(float4*)(dst + 4) = make_float4(o[4], o[5], o[6], o[7]);
    }
}

// ---------------------------------------------------------------------------
// Kernel 3: warp-per-query top-16 with TOTAL ORDER keys:
//   key = (float_bits(d2) << 32) | index
// d2 >= 0 so float bits are monotonic; equal d2 -> lower index wins,
// exactly matching jax.lax.top_k's stable tie-break.
// Each lane keeps a sorted 16-key list over its strided slice, then 16 rounds
// of warp min-key extraction. Output: D float32 [B*NQ*K], then I as float32.
// ---------------------------------------------------------------------------
__global__ __launch_bounds__(256) void select_kernel(float* __restrict__ outD,
                                                     float* __restrict__ outI) {
    int warp = (blockIdx.x * 256 + threadIdx.x) >> 5;
    int lane = threadIdx.x & 31;
    int b = warp / NQ;
    int q = warp % NQ;

    const float* row = g_d2 + ((size_t)b * NQ + q) * NR;

    unsigned long long key[KNN];
#pragma unroll
    for (int j = 0; j < KNN; j++) key[j] = ~0ull;

    for (int c = 0; c < NR / 128; c++) {
        int base = c * 128 + lane * 4;
        float4 v = *(const float4*)(row + base);
        float vv[4] = {v.x, v.y, v.z, v.w};
#pragma unroll
        for (int e = 0; e < 4; e++) {
            unsigned long long kk =
                ((unsigned long long)__float_as_uint(vv[e]) << 32) |
                (unsigned)(base + e);
            if (kk < key[KNN - 1]) {
#pragma unroll
                for (int j = 0; j < KNN; j++) {
                    if (kk < key[j]) {
                        unsigned long long t = key[j]; key[j] = kk; kk = t;
                    }
                }
            }
        }
    }

    float* Do = outD + ((size_t)b * NQ + q) * KNN;
    float* Io = outI + ((size_t)b * NQ + q) * KNN;

    for (int k = 0; k < KNN; k++) {
        unsigned long long h = key[0];
        unsigned long long m = h;
#pragma unroll
        for (int off = 16; off; off >>= 1) {
            unsigned long long o = __shfl_xor_sync(FULLM, m, off);
            if (o < m) m = o;
        }
        if (h == m) {  // unique winner (keys carry unique indices)
#pragma unroll
            for (int j = 0; j < KNN - 1; j++) key[j] = key[j + 1];
            key[KNN - 1] = ~0ull;
        }
        if (lane == 0) {
            Do[k] = sqrtf(__uint_as_float((unsigned)(m >> 32)));
            Io[k] = (float)(unsigned)(m & 0xffffffffull);
        }
    }
}

// ---------------------------------------------------------------------------
extern "C" void kernel_launch(void* const* d_in, const int* in_sizes, int n_in,
                              void* d_out, int out_size) {
    const float* ref   = (const float*)d_in[0];   // [B, NR, DIM]
    const float* query = (const float*)d_in[1];   // [B, NQ, DIM]

    float* outD = (float*)d_out;
    float* outI = outD + (size_t)BATCH * NQ * KNN;

    static const int smem_bytes = (DIM * QS + DIM * RS) * (int)sizeof(float); // 67584
    cudaFuncSetAttribute(gemm_kernel,
                         cudaFuncAttributeMaxDynamicSharedMemorySize, smem_bytes);

    int n_rows = BATCH * NR + BATCH * NQ;              // warp per row
    int n_thr  = n_rows * 32;
    norms_kernel<<<(n_thr + 255) / 256, 256>>>(ref, query);

    dim3 g(NR / TR, NQ / TQ, BATCH);   // (128, 16, 4)
    gemm_kernel<<<g, 256, smem_bytes>>>(ref, query);

    select_kernel<<<(BATCH * NQ) / 8, 256>>>(outD, outI);
}

// round 7
// speedup vs baseline: 1.0555x; 1.0555x over previous
#include <cuda_runtime.h>
#include <math.h>
#include <stdint.h>

#define BATCH 4
#define NQ    2048
#define NR    16384
#define DIM   64
#define KNN   16

#define TQ 128
#define TR 128
#define QS (TQ + 4)
#define RS (TR + 4)
#define DS (TR + 4)          // d2 smem tile stride

#define RCHUNKS 16
#define RCHUNK  (NR / RCHUNKS)      // 1024 refs per block
#define RTILES  (RCHUNK / TR)       // 8 tiles

#define FULLM 0xffffffffu

// Scratch (allocation-free rule: __device__ globals)
__device__ float g_r2[BATCH * NR];
__device__ float g_q2[BATCH * NQ];
// partial top-16 key lists: [b][q][chunk][half][16] u64  -> 32 MB
__device__ unsigned long long g_part[(size_t)BATCH * NQ * RCHUNKS * 2 * KNN];

// ---------------------------------------------------------------------------
// Kernel 1: squared norms (bit-exact XLA-style warp tree; unchanged from R6)
// ---------------------------------------------------------------------------
__global__ void norms_kernel(const float* __restrict__ ref,
                             const float* __restrict__ query) {
    int warp = (blockIdx.x * blockDim.x + threadIdx.x) >> 5;
    int lane = threadIdx.x & 31;
    int total = BATCH * NR + BATCH * NQ;
    if (warp >= total) return;

    const float* row;
    float* out;
    if (warp < BATCH * NR) {
        row = ref + (size_t)warp * DIM;
        out = g_r2 + warp;
    } else {
        int u = warp - BATCH * NR;
        row = query + (size_t)u * DIM;
        out = g_q2 + u;
    }

    float x0 = row[lane];
    float x1 = row[lane + 32];
    float s = __fadd_rn(__fmul_rn(x0, x0), __fmul_rn(x1, x1));
#pragma unroll
    for (int off = 16; off; off >>= 1)
        s = __fadd_rn(s, __shfl_down_sync(FULLM, s, off));
    if (lane == 0) *out = s;
}

// ---------------------------------------------------------------------------
// Kernel 2 (FUSED): per 128q x 1024r chunk: loop 8 r-tiles of 128.
//   GEMM (identical f32x2 FMA chain + exact epilogue as the passing kernel)
//   -> d2 tile in smem -> 2 threads/row scan 64 cols each into private
//   sorted top-16 u64 key lists (key = d2_bits<<32 | global_ref_idx).
// Partial lists written to g_part; no 512MB d2 round-trip.
// ---------------------------------------------------------------------------
__global__ __launch_bounds__(256, 1) void fused_kernel(const float* __restrict__ ref,
                                                       const float* __restrict__ query) {
    extern __shared__ float sm[];
    float* Qs = sm;                      // [DIM][QS]
    float* Rs = sm + DIM * QS;           // [DIM][RS]
    float* Ds = sm + DIM * QS + DIM * RS; // [TQ][DS]

    int b   = blockIdx.z;
    int q0  = blockIdx.y * TQ;
    int cnk = blockIdx.x;
    int rbase = cnk * RCHUNK;
    int tid = threadIdx.x;

    const float* qg = query + ((size_t)b * NQ + q0) * DIM;

    int frow = tid >> 4;
    int fd   = (tid & 15) * 4;

    // Load Q tile once (k-major, padded)
#pragma unroll
    for (int it = 0; it < 8; ++it) {
        int row = frow + it * 16;
        float4 v = *(const float4*)(qg + (size_t)row * DIM + fd);
        Qs[(fd + 0) * QS + row] = v.x;
        Qs[(fd + 1) * QS + row] = v.y;
        Qs[(fd + 2) * QS + row] = v.z;
        Qs[(fd + 3) * QS + row] = v.w;
    }

    int qy = (tid >> 4) * 8;
    int rx = (tid & 15) * 8;

    int srow  = tid >> 1;        // selection: row 0..127
    int shalf = tid & 1;         // scans cols [shalf*64, shalf*64+64)

    unsigned long long key[KNN];
#pragma unroll
    for (int j = 0; j < KNN; j++) key[j] = ~0ull;

    float q2v_sel = 0.f;  // not needed; epilogue handles q2/r2

    for (int t = 0; t < RTILES; t++) {
        int r0 = rbase + t * TR;
        const float* rg = ref + ((size_t)b * NR + r0) * DIM;

        // Load R tile
#pragma unroll
        for (int it = 0; it < 8; ++it) {
            int row = frow + it * 16;
            float4 w = *(const float4*)(rg + (size_t)row * DIM + fd);
            Rs[(fd + 0) * RS + row] = w.x;
            Rs[(fd + 1) * RS + row] = w.y;
            Rs[(fd + 2) * RS + row] = w.z;
            Rs[(fd + 3) * RS + row] = w.w;
        }
        __syncthreads();   // R (and on t=0, Q) ready; prior scan done

        unsigned long long acc[8][4];
#pragma unroll
        for (int i = 0; i < 8; i++)
#pragma unroll
            for (int j = 0; j < 4; j++) acc[i][j] = 0ull;

#pragma unroll 8
        for (int k = 0; k < DIM; k++) {
            float4 qa = *(const float4*)(Qs + k * QS + qy);
            float4 qb = *(const float4*)(Qs + k * QS + qy + 4);
            double2 ra = *(const double2*)(Rs + k * RS + rx);
            double2 rb = *(const double2*)(Rs + k * RS + rx + 4);
            unsigned long long r[4];
            r[0] = __double_as_longlong(ra.x);
            r[1] = __double_as_longlong(ra.y);
            r[2] = __double_as_longlong(rb.x);
            r[3] = __double_as_longlong(rb.y);
            float qv[8] = {qa.x, qa.y, qa.z, qa.w, qb.x, qb.y, qb.z, qb.w};
#pragma unroll
            for (int i = 0; i < 8; i++) {
                unsigned long long qd;
                unsigned qu = __float_as_uint(qv[i]);
                asm("mov.b64 %0, {%1, %1};" : "=l"(qd) : "r"(qu));
#pragma unroll
                for (int j = 0; j < 4; j++) {
                    asm("fma.rn.f32x2 %0, %1, %2, %0;"
                        : "+l"(acc[i][j]) : "l"(qd), "l"(r[j]));
                }
            }
        }

        // Exact epilogue -> smem d2 tile
        float r2v[8];
#pragma unroll
        for (int j = 0; j < 8; j++) r2v[j] = g_r2[b * NR + r0 + rx + j];

#pragma unroll
        for (int i = 0; i < 8; i++) {
            float q2v = g_q2[b * NQ + q0 + qy + i];
            float o[8];
#pragma unroll
            for (int j = 0; j < 4; j++) {
                unsigned long long a = acc[i][j];
                float lo = __uint_as_float((unsigned)(a & 0xffffffffull));
                float hi = __uint_as_float((unsigned)(a >> 32));
                float t0 = __fadd_rn(q2v, r2v[2 * j + 0]);
                float t1 = __fadd_rn(q2v, r2v[2 * j + 1]);
                o[2 * j + 0] = fmaxf(__fmaf_rn(-2.f, lo, t0), 0.f);
                o[2 * j + 1] = fmaxf(__fmaf_rn(-2.f, hi, t1), 0.f);
            }
            float* dst = Ds + (qy + i) * DS + rx;
            *(float4*)(dst + 0) = make_float4(o[0], o[1], o[2], o[3]);
            *(float4*)(dst + 4) = make_float4(o[4], o[5], o[6], o[7]);
        }
        __syncthreads();   // Ds complete

        // Selection scan: 64 values per thread, total-order keys
        const float* drow = Ds + srow * DS + shalf * 64;
        int gidx0 = r0 + shalf * 64;
#pragma unroll 16
        for (int i = 0; i < 64; i++) {
            float val = drow[i];
            unsigned long long kk =
                ((unsigned long long)__float_as_uint(val) << 32) |
                (unsigned)(gidx0 + i);
            if (kk < key[KNN - 1]) {
#pragma unroll
                for (int j = 0; j < KNN; j++) {
                    if (kk < key[j]) {
                        unsigned long long tt = key[j]; key[j] = kk; kk = tt;
                    }
                }
            }
        }
        __syncthreads();   // scan done before next tile overwrites Ds
    }

    // Write partial list
    unsigned long long* dst = g_part +
        ((((size_t)(b * NQ + q0 + srow)) * RCHUNKS + cnk) * 2 + shalf) * KNN;
#pragma unroll
    for (int j = 0; j < KNN; j++) dst[j] = key[j];
}

// ---------------------------------------------------------------------------
// Kernel 3: final merge. Warp per query: 512 partial keys -> top-16.
// Each lane sorted-inserts 16 keys, then 16 rounds of warp min-extraction.
// Output: D float32 [B*NQ*K] then I as float32 [B*NQ*K].
// ---------------------------------------------------------------------------
__global__ __launch_bounds__(256) void merge_kernel(float* __restrict__ outD,
                                                    float* __restrict__ outI) {
    int warp = (blockIdx.x * 256 + threadIdx.x) >> 5;
    int lane = threadIdx.x & 31;

    const unsigned long long* src = g_part + (size_t)warp * RCHUNKS * 2 * KNN;

    unsigned long long key[KNN];
#pragma unroll
    for (int j = 0; j < KNN; j++) key[j] = ~0ull;

#pragma unroll
    for (int i = 0; i < 16; i++) {
        unsigned long long kk = src[lane * 16 + i];
        if (kk < key[KNN - 1]) {
#pragma unroll
            for (int j = 0; j < KNN; j++) {
                if (kk < key[j]) {
                    unsigned long long tt = key[j]; key[j] = kk; kk = tt;
                }
            }
        }
    }

    float* Do = outD + (size_t)warp * KNN;
    float* Io = outI + (size_t)warp * KNN;

    for (int k = 0; k < KNN; k++) {
        unsigned long long h = key[0];
        unsigned long long m = h;
#pragma unroll
        for (int off = 16; off; off >>= 1) {
            unsigned long long o = __shfl_xor_sync(FULLM, m, off);
            if (o < m) m = o;
        }
        if (h == m) {   // unique winner (keys carry unique indices)
#pragma unroll
            for (int j = 0; j < KNN - 1; j++) key[j] = key[j + 1];
            key[KNN - 1] = ~0ull;
        }
        if (lane == 0) {
            Do[k] = sqrtf(__uint_as_float((unsigned)(m >> 32)));
            Io[k] = (float)(unsigned)(m & 0xffffffffull);
        }
    }
}

// ---------------------------------------------------------------------------
extern "C" void kernel_launch(void* const* d_in, const int* in_sizes, int n_in,
                              void* d_out, int out_size) {
    const float* ref   = (const float*)d_in[0];   // [B, NR, DIM]
    const float* query = (const float*)d_in[1];   // [B, NQ, DIM]

    float* outD = (float*)d_out;
    float* outI = outD + (size_t)BATCH * NQ * KNN;

    static const int smem_bytes =
        (DIM * QS + DIM * RS + TQ * DS) * (int)sizeof(float);  // 135168
    cudaFuncSetAttribute(fused_kernel,
                         cudaFuncAttributeMaxDynamicSharedMemorySize, smem_bytes);

    int n_rows = BATCH * NR + BATCH * NQ;
    int n_thr  = n_rows * 32;
    norms_kernel<<<(n_thr + 255) / 256, 256>>>(ref, query);

    dim3 g(RCHUNKS, NQ / TQ, BATCH);   // (16, 16, 4) = 1024 blocks
    fused_kernel<<<g, 256, smem_bytes>>>(ref, query);

    merge_kernel<<<(BATCH * NQ * 32) / 256, 256>>>(outD, outI);
}

// round 8
// speedup vs baseline: 1.0830x; 1.0261x over previous
#include <cuda_runtime.h>
#include <math.h>
#include <stdint.h>

#define BATCH 4
#define NQ    2048
#define NR    16384
#define DIM   64
#define KNN   16

#define TQ 128
#define TR 128
#define QS (TQ + 4)
#define RS (TR + 4)
#define DS (TR + 4)

#define RCHUNKS 16
#define RCHUNK  (NR / RCHUNKS)      // 1024 refs per block
#define RTILES  (RCHUNK / TR)       // 8 tiles

#define FULLM 0xffffffffu

// Scratch (allocation-free rule: __device__ globals)
__device__ float g_r2[BATCH * NR];
__device__ float g_q2[BATCH * NQ];
// partial top-16 key lists: [b][q][chunk][half][16] u64  -> 32 MB
__device__ unsigned long long g_part[(size_t)BATCH * NQ * RCHUNKS * 2 * KNN];

// ---------------------------------------------------------------------------
// Kernel 1: squared norms (bit-exact XLA-style warp tree; validated)
// ---------------------------------------------------------------------------
__global__ void norms_kernel(const float* __restrict__ ref,
                             const float* __restrict__ query) {
    int warp = (blockIdx.x * blockDim.x + threadIdx.x) >> 5;
    int lane = threadIdx.x & 31;
    int total = BATCH * NR + BATCH * NQ;
    if (warp >= total) return;

    const float* row;
    float* out;
    if (warp < BATCH * NR) {
        row = ref + (size_t)warp * DIM;
        out = g_r2 + warp;
    } else {
        int u = warp - BATCH * NR;
        row = query + (size_t)u * DIM;
        out = g_q2 + u;
    }

    float x0 = row[lane];
    float x1 = row[lane + 32];
    float s = __fadd_rn(__fmul_rn(x0, x0), __fmul_rn(x1, x1));
#pragma unroll
    for (int off = 16; off; off >>= 1)
        s = __fadd_rn(s, __shfl_down_sync(FULLM, s, off));
    if (lane == 0) *out = s;
}

// ---------------------------------------------------------------------------
// Kernel 2 (FUSED, conflict-free mapping): per 128q x 1024r chunk, 8 r-tiles.
// Thread (ty=tid>>4, tx=tid&15): queries qy..qy+7, refs {tx*4..+3, 64+tx*4..+3}
//  -> all Rs LDS are double2 at 16B lane stride (conflict-free),
//     Ds stores float4 coalesced. Arithmetic identical to passing kernel.
// ---------------------------------------------------------------------------
__global__ __launch_bounds__(256, 1) void fused_kernel(const float* __restrict__ ref,
                                                       const float* __restrict__ query) {
    extern __shared__ float sm[];
    float* Qs  = sm;                                // [DIM][QS]
    float* Rs  = sm + DIM * QS;                     // [DIM][RS]
    float* Ds  = sm + DIM * QS + DIM * RS;          // [TQ][DS]
    float* r2s = sm + DIM * QS + DIM * RS + TQ * DS; // [RCHUNK]

    int b   = blockIdx.z;
    int q0  = blockIdx.y * TQ;
    int cnk = blockIdx.x;
    int rbase = cnk * RCHUNK;
    int tid = threadIdx.x;

    const float* qg = query + ((size_t)b * NQ + q0) * DIM;

    int frow = tid >> 4;
    int fd   = (tid & 15) * 4;

    // Load Q tile once (k-major, padded)
#pragma unroll
    for (int it = 0; it < 8; ++it) {
        int row = frow + it * 16;
        float4 v = *(const float4*)(qg + (size_t)row * DIM + fd);
        Qs[(fd + 0) * QS + row] = v.x;
        Qs[(fd + 1) * QS + row] = v.y;
        Qs[(fd + 2) * QS + row] = v.z;
        Qs[(fd + 3) * QS + row] = v.w;
    }

    // Stage r2 for the whole chunk (1024 floats), one float4 per thread
    {
        float4 v = *(const float4*)(g_r2 + b * NR + rbase + tid * 4);
        *(float4*)(r2s + tid * 4) = v;
    }

    int qy  = (tid >> 4) * 8;
    int tx4 = (tid & 15) * 4;

    // Hoist q2 (constant across tiles)
    float q2v[8];
#pragma unroll
    for (int i = 0; i < 8; i++) q2v[i] = g_q2[b * NQ + q0 + qy + i];

    int srow  = tid >> 1;
    int shalf = tid & 1;

    unsigned long long key[KNN];
#pragma unroll
    for (int j = 0; j < KNN; j++) key[j] = ~0ull;

    for (int t = 0; t < RTILES; t++) {
        int r0 = rbase + t * TR;
        const float* rg = ref + ((size_t)b * NR + r0) * DIM;

        // Load R tile (k-major, padded)
#pragma unroll
        for (int it = 0; it < 8; ++it) {
            int row = frow + it * 16;
            float4 w = *(const float4*)(rg + (size_t)row * DIM + fd);
            Rs[(fd + 0) * RS + row] = w.x;
            Rs[(fd + 1) * RS + row] = w.y;
            Rs[(fd + 2) * RS + row] = w.z;
            Rs[(fd + 3) * RS + row] = w.w;
        }
        __syncthreads();   // R ready (and Q/r2s on t=0); prior scan done

        unsigned long long acc[8][4];
#pragma unroll
        for (int i = 0; i < 8; i++)
#pragma unroll
            for (int j = 0; j < 4; j++) acc[i][j] = 0ull;

#pragma unroll 4
        for (int k = 0; k < DIM; k++) {
            float4 qa = *(const float4*)(Qs + k * QS + qy);
            float4 qb = *(const float4*)(Qs + k * QS + qy + 4);
            double2 rA = *(const double2*)(Rs + k * RS + tx4);       // refs tx4..tx4+3
            double2 rB = *(const double2*)(Rs + k * RS + tx4 + 64);  // refs 64+tx4..+3
            unsigned long long r[4];
            r[0] = __double_as_longlong(rA.x);   // (tx4,   tx4+1)
            r[1] = __double_as_longlong(rA.y);   // (tx4+2, tx4+3)
            r[2] = __double_as_longlong(rB.x);   // (64+tx4,   +1)
            r[3] = __double_as_longlong(rB.y);   // (64+tx4+2, +3)
            float qv[8] = {qa.x, qa.y, qa.z, qa.w, qb.x, qb.y, qb.z, qb.w};
#pragma unroll
            for (int i = 0; i < 8; i++) {
                unsigned long long qd;
                unsigned qu = __float_as_uint(qv[i]);
                asm("mov.b64 %0, {%1, %1};" : "=l"(qd) : "r"(qu));
#pragma unroll
                for (int j = 0; j < 4; j++) {
                    asm("fma.rn.f32x2 %0, %1, %2, %0;"
                        : "+l"(acc[i][j]) : "l"(qd), "l"(r[j]));
                }
            }
        }

        // Exact epilogue -> smem d2 tile (same rounding sequence as validated)
        int c0 = t * TR + tx4;  // local chunk col of first ref
        float r2a0 = r2s[c0 + 0], r2a1 = r2s[c0 + 1];
        float r2a2 = r2s[c0 + 2], r2a3 = r2s[c0 + 3];
        float r2b0 = r2s[c0 + 64], r2b1 = r2s[c0 + 65];
        float r2b2 = r2s[c0 + 66], r2b3 = r2s[c0 + 67];

#pragma unroll
        for (int i = 0; i < 8; i++) {
            float o[8];
            {
                unsigned long long a = acc[i][0];
                float lo = __uint_as_float((unsigned)(a & 0xffffffffull));
                float hi = __uint_as_float((unsigned)(a >> 32));
                o[0] = fmaxf(__fmaf_rn(-2.f, lo, __fadd_rn(q2v[i], r2a0)), 0.f);
                o[1] = fmaxf(__fmaf_rn(-2.f, hi, __fadd_rn(q2v[i], r2a1)), 0.f);
            }
            {
                unsigned long long a = acc[i][1];
                float lo = __uint_as_float((unsigned)(a & 0xffffffffull));
                float hi = __uint_as_float((unsigned)(a >> 32));
                o[2] = fmaxf(__fmaf_rn(-2.f, lo, __fadd_rn(q2v[i], r2a2)), 0.f);
                o[3] = fmaxf(__fmaf_rn(-2.f, hi, __fadd_rn(q2v[i], r2a3)), 0.f);
            }
            {
                unsigned long long a = acc[i][2];
                float lo = __uint_as_float((unsigned)(a & 0xffffffffull));
                float hi = __uint_as_float((unsigned)(a >> 32));
                o[4] = fmaxf(__fmaf_rn(-2.f, lo, __fadd_rn(q2v[i], r2b0)), 0.f);
                o[5] = fmaxf(__fmaf_rn(-2.f, hi, __fadd_rn(q2v[i], r2b1)), 0.f);
            }
            {
                unsigned long long a = acc[i][3];
                float lo = __uint_as_float((unsigned)(a & 0xffffffffull));
                float hi = __uint_as_float((unsigned)(a >> 32));
                o[6] = fmaxf(__fmaf_rn(-2.f, lo, __fadd_rn(q2v[i], r2b2)), 0.f);
                o[7] = fmaxf(__fmaf_rn(-2.f, hi, __fadd_rn(q2v[i], r2b3)), 0.f);
            }
            float* dst = Ds + (qy + i) * DS + tx4;
            *(float4*)(dst + 0)  = make_float4(o[0], o[1], o[2], o[3]);
            *(float4*)(dst + 64) = make_float4(o[4], o[5], o[6], o[7]);
        }
        __syncthreads();   // Ds complete

        // Selection scan: 64 values per thread via float4, total-order keys
        const float* drow = Ds + srow * DS + shalf * 64;
        int gidx0 = r0 + shalf * 64;
#pragma unroll 4
        for (int it = 0; it < 16; it++) {
            float4 v = *(const float4*)(drow + it * 4);
            float vv[4] = {v.x, v.y, v.z, v.w};
#pragma unroll
            for (int e = 0; e < 4; e++) {
                unsigned long long kk =
                    ((unsigned long long)__float_as_uint(vv[e]) << 32) |
                    (unsigned)(gidx0 + it * 4 + e);
                if (kk < key[KNN - 1]) {
#pragma unroll
                    for (int j = 0; j < KNN; j++) {
                        if (kk < key[j]) {
                            unsigned long long tt = key[j]; key[j] = kk; kk = tt;
                        }
                    }
                }
            }
        }
        __syncthreads();   // scan done before next tile overwrites Ds
    }

    unsigned long long* dst = g_part +
        ((((size_t)(b * NQ + q0 + srow)) * RCHUNKS + cnk) * 2 + shalf) * KNN;
#pragma unroll
    for (int j = 0; j < KNN; j++) dst[j] = key[j];
}

// ---------------------------------------------------------------------------
// Kernel 3: final merge. Warp per query: 512 partial keys -> top-16.
// ---------------------------------------------------------------------------
__global__ __launch_bounds__(256) void merge_kernel(float* __restrict__ outD,
                                                    float* __restrict__ outI) {
    int warp = (blockIdx.x * 256 + threadIdx.x) >> 5;
    int lane = threadIdx.x & 31;

    const unsigned long long* src = g_part + (size_t)warp * RCHUNKS * 2 * KNN;

    unsigned long long key[KNN];
#pragma unroll
    for (int j = 0; j < KNN; j++) key[j] = ~0ull;

#pragma unroll
    for (int i = 0; i < 16; i++) {
        unsigned long long kk = src[lane * 16 + i];
        if (kk < key[KNN - 1]) {
#pragma unroll
            for (int j = 0; j < KNN; j++) {
                if (kk < key[j]) {
                    unsigned long long tt = key[j]; key[j] = kk; kk = tt;
                }
            }
        }
    }

    float* Do = outD + (size_t)warp * KNN;
    float* Io = outI + (size_t)warp * KNN;

    for (int k = 0; k < KNN; k++) {
        unsigned long long h = key[0];
        unsigned long long m = h;
#pragma unroll
        for (int off = 16; off; off >>= 1) {
            unsigned long long o = __shfl_xor_sync(FULLM, m, off);
            if (o < m) m = o;
        }
        if (h == m) {
#pragma unroll
            for (int j = 0; j < KNN - 1; j++) key[j] = key[j + 1];
            key[KNN - 1] = ~0ull;
        }
        if (lane == 0) {
            Do[k] = sqrtf(__uint_as_float((unsigned)(m >> 32)));
            Io[k] = (float)(unsigned)(m & 0xffffffffull);
        }
    }
}

// ---------------------------------------------------------------------------
extern "C" void kernel_launch(void* const* d_in, const int* in_sizes, int n_in,
                              void* d_out, int out_size) {
    const float* ref   = (const float*)d_in[0];   // [B, NR, DIM]
    const float* query = (const float*)d_in[1];   // [B, NQ, DIM]

    float* outD = (float*)d_out;
    float* outI = outD + (size_t)BATCH * NQ * KNN;

    static const int smem_bytes =
        (DIM * QS + DIM * RS + TQ * DS + RCHUNK) * (int)sizeof(float);  // 139264
    cudaFuncSetAttribute(fused_kernel,
                         cudaFuncAttributeMaxDynamicSharedMemorySize, smem_bytes);

    int n_rows = BATCH * NR + BATCH * NQ;
    int n_thr  = n_rows * 32;
    norms_kernel<<<(n_thr + 255) / 256, 256>>>(ref, query);

    dim3 g(RCHUNKS, NQ / TQ, BATCH);   // (16, 16, 4) = 1024 blocks
    fused_kernel<<<g, 256, smem_bytes>>>(ref, query);

    merge_kernel<<<(BATCH * NQ * 32) / 256, 256>>>(outD, outI);
}

// round 10
// speedup vs baseline: 1.3531x; 1.2494x over previous
#include <cuda_runtime.h>
#include <cuda_bf16.h>
#include <math.h>
#include <stdint.h>

#define BATCH 4
#define NQ    2048
#define NR    16384
#define DIM   64
#define KNN   16

#define TQ 128
#define TR 128
#define QHS 72            // bf16 row stride for Q tile (64 + 8 pad)
#define RHS 72            // bf16 row stride for R tile
#define DS  132           // fp32 row stride for d2 tile

#define RCHUNKS 16
#define RCHUNK  (NR / RCHUNKS)      // 1024 refs per block
#define RTILES  (RCHUNK / TR)       // 8 tiles
#define NCAND   32                  // approx candidates rescored exactly

#define FULLM 0xffffffffu

// Scratch (allocation-free rule: __device__ globals)
__device__ float g_r2[BATCH * NR];
__device__ float g_q2[BATCH * NQ];
// partial approx top-16 key lists: [b][q][chunk][half][16] u64 -> 32 MB
__device__ unsigned long long g_part[(size_t)BATCH * NQ * RCHUNKS * 2 * KNN];

// ---------------------------------------------------------------------------
// Kernel 1: squared norms (bit-exact XLA-style warp tree; validated)
// ---------------------------------------------------------------------------
__global__ void norms_kernel(const float* __restrict__ ref,
                             const float* __restrict__ query) {
    int warp = (blockIdx.x * blockDim.x + threadIdx.x) >> 5;
    int lane = threadIdx.x & 31;
    int total = BATCH * NR + BATCH * NQ;
    if (warp >= total) return;

    const float* row;
    float* out;
    if (warp < BATCH * NR) {
        row = ref + (size_t)warp * DIM;
        out = g_r2 + warp;
    } else {
        int u = warp - BATCH * NR;
        row = query + (size_t)u * DIM;
        out = g_q2 + u;
    }

    float x0 = row[lane];
    float x1 = row[lane + 32];
    float s = __fadd_rn(__fmul_rn(x0, x0), __fmul_rn(x1, x1));
#pragma unroll
    for (int off = 16; off; off >>= 1)
        s = __fadd_rn(s, __shfl_down_sync(FULLM, s, off));
    if (lane == 0) *out = s;
}

// ---------------------------------------------------------------------------
// mma.sync m16n8k16 bf16 (A row-major, B col-major, fp32 accum)
// ---------------------------------------------------------------------------
__device__ __forceinline__ void mma_bf16(float c[4],
                                         const uint32_t a[4],
                                         uint32_t b0, uint32_t b1) {
    asm volatile(
        "mma.sync.aligned.m16n8k16.row.col.f32.bf16.bf16.f32 "
        "{%0,%1,%2,%3}, {%4,%5,%6,%7}, {%8,%9}, {%0,%1,%2,%3};"
        : "+f"(c[0]), "+f"(c[1]), "+f"(c[2]), "+f"(c[3])
        : "r"(a[0]), "r"(a[1]), "r"(a[2]), "r"(a[3]), "r"(b0), "r"(b1));
}

// ---------------------------------------------------------------------------
// Kernel 2 (FUSED, tensor-core candidate pass): per 128q x 1024r chunk.
// Q/R tiles converted to bf16 in smem; 8 warps (4 q-rows x 2 r-cols), each
// warp 32q x 64r via m16n8k16. Approx d2 -> Ds -> per-lane top-16 key scan.
// ---------------------------------------------------------------------------
__global__ __launch_bounds__(256, 1) void fused_kernel(const float* __restrict__ ref,
                                                       const float* __restrict__ query) {
    extern __shared__ char smraw[];
    uint16_t* Qh = (uint16_t*)smraw;                               // [TQ][QHS]
    uint16_t* Rh = (uint16_t*)(smraw + TQ * QHS * 2);              // [TR][RHS]
    float*    Dsm = (float*)(smraw + TQ * QHS * 2 + TR * RHS * 2); // [TQ][DS]
    float*    r2s = (float*)(smraw + TQ * QHS * 2 + TR * RHS * 2
                             + TQ * DS * 4);                       // [RCHUNK]

    int b   = blockIdx.z;
    int q0  = blockIdx.y * TQ;
    int cnk = blockIdx.x;
    int rbase = cnk * RCHUNK;
    int tid = threadIdx.x;

    int frow = tid >> 4;
    int fd   = (tid & 15) * 4;

    // Q tile -> bf16 smem (rn rounding)
    const float* qg = query + ((size_t)b * NQ + q0) * DIM;
#pragma unroll
    for (int it = 0; it < 8; ++it) {
        int row = frow + it * 16;
        float4 v = *(const float4*)(qg + (size_t)row * DIM + fd);
        __nv_bfloat162 p0 = __floats2bfloat162_rn(v.x, v.y);
        __nv_bfloat162 p1 = __floats2bfloat162_rn(v.z, v.w);
        uint2 u;
        u.x = *(uint32_t*)&p0;
        u.y = *(uint32_t*)&p1;
        *(uint2*)&Qh[row * QHS + fd] = u;
    }
    // stage r2 chunk
    {
        float4 v = *(const float4*)(g_r2 + b * NR + rbase + tid * 4);
        *(float4*)(r2s + tid * 4) = v;
    }

    int warp = tid >> 5;
    int lane = tid & 31;
    int g  = lane >> 2;
    int t2 = (lane & 3) * 2;
    int wq = (warp >> 1) * 32;   // warp q base within tile
    int wr = (warp & 1) * 64;    // warp r base within tile

    // hoist exact q2 for this thread's output rows
    float q2v[2][2];
#pragma unroll
    for (int mt = 0; mt < 2; mt++) {
        q2v[mt][0] = g_q2[b * NQ + q0 + wq + mt * 16 + g];
        q2v[mt][1] = g_q2[b * NQ + q0 + wq + mt * 16 + g + 8];
    }

    int srow  = tid >> 1;
    int shalf = tid & 1;

    unsigned long long key[KNN];
#pragma unroll
    for (int j = 0; j < KNN; j++) key[j] = ~0ull;

    for (int t = 0; t < RTILES; t++) {
        int r0 = rbase + t * TR;
        const float* rg = ref + ((size_t)b * NR + r0) * DIM;

        // R tile -> bf16 smem
#pragma unroll
        for (int it = 0; it < 8; ++it) {
            int row = frow + it * 16;
            float4 v = *(const float4*)(rg + (size_t)row * DIM + fd);
            __nv_bfloat162 p0 = __floats2bfloat162_rn(v.x, v.y);
            __nv_bfloat162 p1 = __floats2bfloat162_rn(v.z, v.w);
            uint2 u;
            u.x = *(uint32_t*)&p0;
            u.y = *(uint32_t*)&p1;
            *(uint2*)&Rh[row * RHS + fd] = u;
        }
        __syncthreads();   // tiles ready; also: all scans of prev Ds done

        float c[2][8][4];
#pragma unroll
        for (int mt = 0; mt < 2; mt++)
#pragma unroll
            for (int nt = 0; nt < 8; nt++)
#pragma unroll
                for (int e = 0; e < 4; e++) c[mt][nt][e] = 0.f;

#pragma unroll
        for (int ks = 0; ks < 4; ks++) {
            int k0 = ks * 16;
            uint32_t a[2][4];
#pragma unroll
            for (int mt = 0; mt < 2; mt++) {
                const uint16_t* ap = &Qh[(wq + mt * 16 + g) * QHS + k0 + t2];
                a[mt][0] = *(const uint32_t*)ap;
                a[mt][1] = *(const uint32_t*)(ap + 8 * QHS);
                a[mt][2] = *(const uint32_t*)(ap + 8);
                a[mt][3] = *(const uint32_t*)(ap + 8 * QHS + 8);
            }
#pragma unroll
            for (int nt = 0; nt < 8; nt++) {
                const uint16_t* bp = &Rh[(wr + nt * 8 + g) * RHS + k0 + t2];
                uint32_t b0 = *(const uint32_t*)bp;
                uint32_t b1 = *(const uint32_t*)(bp + 8);
                mma_bf16(c[0][nt], a[0], b0, b1);
                mma_bf16(c[1][nt], a[1], b0, b1);
            }
        }

        // approx epilogue: d2 = max(q2 + r2 - 2*dot, 0) -> Ds
#pragma unroll
        for (int mt = 0; mt < 2; mt++) {
#pragma unroll
            for (int nt = 0; nt < 8; nt++) {
                int rc = t * TR + wr + nt * 8 + t2;   // chunk-local ref col
                float rA = r2s[rc];
                float rB = r2s[rc + 1];
                float d0 = fmaxf(__fmaf_rn(-2.f, c[mt][nt][0], __fadd_rn(q2v[mt][0], rA)), 0.f);
                float d1 = fmaxf(__fmaf_rn(-2.f, c[mt][nt][1], __fadd_rn(q2v[mt][0], rB)), 0.f);
                float d2_ = fmaxf(__fmaf_rn(-2.f, c[mt][nt][2], __fadd_rn(q2v[mt][1], rA)), 0.f);
                float d3 = fmaxf(__fmaf_rn(-2.f, c[mt][nt][3], __fadd_rn(q2v[mt][1], rB)), 0.f);
                int qrow = wq + mt * 16 + g;
                int rcol = wr + nt * 8 + t2;
                *(float2*)&Dsm[qrow * DS + rcol]       = make_float2(d0, d1);
                *(float2*)&Dsm[(qrow + 8) * DS + rcol] = make_float2(d2_, d3);
            }
        }
        __syncthreads();   // Ds complete

        // selection scan: 64 approx values per thread, total-order keys
        const float* drow = Dsm + srow * DS + shalf * 64;
        int gidx0 = r0 + shalf * 64;
#pragma unroll 4
        for (int it = 0; it < 16; it++) {
            float4 v = *(const float4*)(drow + it * 4);
            float vv[4] = {v.x, v.y, v.z, v.w};
#pragma unroll
            for (int e = 0; e < 4; e++) {
                unsigned long long kk =
                    ((unsigned long long)__float_as_uint(vv[e]) << 32) |
                    (unsigned)(gidx0 + it * 4 + e);
                if (kk < key[KNN - 1]) {
#pragma unroll
                    for (int j = 0; j < KNN; j++) {
                        if (kk < key[j]) {
                            unsigned long long tt = key[j]; key[j] = kk; kk = tt;
                        }
                    }
                }
            }
        }
        // next iteration's first __syncthreads orders scan vs tile overwrite
    }

    unsigned long long* dst = g_part +
        ((((size_t)(b * NQ + q0 + srow)) * RCHUNKS + cnk) * 2 + shalf) * KNN;
#pragma unroll
    for (int j = 0; j < KNN; j++) dst[j] = key[j];
}

// ---------------------------------------------------------------------------
// Kernel 3: merge approx partials -> top-32 candidates -> EXACT rescore
// (validated sequential-k FMA chain + exact epilogue) -> exact top-16 out.
// Warp per query.
// ---------------------------------------------------------------------------
__global__ __launch_bounds__(256) void merge_kernel(const float* __restrict__ ref,
                                                    const float* __restrict__ query,
                                                    float* __restrict__ outD,
                                                    float* __restrict__ outI) {
    __shared__ float qs[8][DIM];

    int gwarp = (blockIdx.x * 256 + threadIdx.x) >> 5;
    int w     = (threadIdx.x >> 5) & 7;
    int lane  = threadIdx.x & 31;
    int b = gwarp / NQ;
    int q = gwarp % NQ;

    // stage query row in smem (broadcast reads later)
    const float* qrow = query + ((size_t)b * NQ + q) * DIM;
    {
        float2 v = *(const float2*)(qrow + lane * 2);
        qs[w][lane * 2 + 0] = v.x;
        qs[w][lane * 2 + 1] = v.y;
    }
    __syncwarp();

    // gather 512 approx partial keys -> per-lane sorted top-16
    const unsigned long long* src = g_part + (size_t)gwarp * RCHUNKS * 2 * KNN;
    unsigned long long key[KNN];
#pragma unroll
    for (int j = 0; j < KNN; j++) key[j] = ~0ull;
#pragma unroll
    for (int i = 0; i < 16; i++) {
        unsigned long long kk = src[lane * 16 + i];
        if (kk < key[KNN - 1]) {
#pragma unroll
            for (int j = 0; j < KNN; j++) {
                if (kk < key[j]) {
                    unsigned long long tt = key[j]; key[j] = kk; kk = tt;
                }
            }
        }
    }

    // extract approx top-32; candidate r lands in lane r
    unsigned long long cand = ~0ull;
    for (int r = 0; r < NCAND; r++) {
        unsigned long long m = key[0];
#pragma unroll
        for (int off = 16; off; off >>= 1) {
            unsigned long long o = __shfl_xor_sync(FULLM, m, off);
            if (o < m) m = o;
        }
        if (key[0] == m) {   // unique winner pops
#pragma unroll
            for (int j = 0; j < KNN - 1; j++) key[j] = key[j + 1];
            key[KNN - 1] = ~0ull;
        }
        if (lane == r) cand = m;
    }
    int cidx = (int)(unsigned)(cand & 0xffffffffull);

    // exact rescore (bit-identical to validated pipeline)
    const float* rrow = ref + ((size_t)b * NR + cidx) * DIM;
    float dot = 0.f;
#pragma unroll
    for (int k4 = 0; k4 < DIM / 4; k4++) {
        float4 rv = *(const float4*)(rrow + k4 * 4);
        dot = __fmaf_rn(qs[w][k4 * 4 + 0], rv.x, dot);
        dot = __fmaf_rn(qs[w][k4 * 4 + 1], rv.y, dot);
        dot = __fmaf_rn(qs[w][k4 * 4 + 2], rv.z, dot);
        dot = __fmaf_rn(qs[w][k4 * 4 + 3], rv.w, dot);
    }
    float q2v = g_q2[b * NQ + q];
    float r2v = g_r2[b * NR + cidx];
    float d2 = fmaxf(__fmaf_rn(-2.f, dot, __fadd_rn(q2v, r2v)), 0.f);
    unsigned long long ekey =
        ((unsigned long long)__float_as_uint(d2) << 32) | (unsigned)cidx;

    float* Do = outD + (size_t)gwarp * KNN;
    float* Io = outI + (size_t)gwarp * KNN;

    for (int k = 0; k < KNN; k++) {
        unsigned long long m = ekey;
#pragma unroll
        for (int off = 16; off; off >>= 1) {
            unsigned long long o = __shfl_xor_sync(FULLM, m, off);
            if (o < m) m = o;
        }
        if (ekey == m) ekey = ~0ull;   // winner retires
        if (lane == 0) {
            Do[k] = sqrtf(__uint_as_float((unsigned)(m >> 32)));
            Io[k] = (float)(unsigned)(m & 0xffffffffull);
        }
    }
}

// ---------------------------------------------------------------------------
extern "C" void kernel_launch(void* const* d_in, const int* in_sizes, int n_in,
                              void* d_out, int out_size) {
    const float* ref   = (const float*)d_in[0];   // [B, NR, DIM]
    const float* query = (const float*)d_in[1];   // [B, NQ, DIM]

    float* outD = (float*)d_out;
    float* outI = outD + (size_t)BATCH * NQ * KNN;

    static const int smem_bytes =
        TQ * QHS * 2 + TR * RHS * 2 + TQ * DS * 4 + RCHUNK * 4;  // 108544
    cudaFuncSetAttribute(fused_kernel,
                         cudaFuncAttributeMaxDynamicSharedMemorySize, smem_bytes);

    int n_rows = BATCH * NR + BATCH * NQ;
    int n_thr  = n_rows * 32;
    norms_kernel<<<(n_thr + 255) / 256, 256>>>(ref, query);

    dim3 g(RCHUNKS, NQ / TQ, BATCH);   // (16, 16, 4) = 1024 blocks
    fused_kernel<<<g, 256, smem_bytes>>>(ref, query);

    merge_kernel<<<(BATCH * NQ * 32) / 256, 256>>>(ref, query, outD, outI);
}

// round 11
// speedup vs baseline: 2.7739x; 2.0501x over previous
#include <cuda_runtime.h>
#include <cuda_bf16.h>
#include <math.h>
#include <stdint.h>

#define BATCH 4
#define NQ    2048
#define NR    16384
#define DIM   64
#define KNN   16

#define TQ 128
#define TR 128
#define QHS 72            // bf16 row stride (64 + 8 pad)
#define RHS 72

#define RCHUNKS 16
#define RCHUNK  (NR / RCHUNKS)      // 1024 refs per block
#define RTILES  (RCHUNK / TR)       // 8 tiles
#define TSEL  8                      // per-(thread,qrow) approx top-T
#define NSLICE 8                     // slices per (query, chunk)
#define NCAND 32                     // approx candidates rescored exactly

#define FULLM 0xffffffffu
#define INF_F __int_as_float(0x7f800000)

// Scratch (allocation-free rule: __device__ globals)
__device__ float g_r2[BATCH * NR];
__device__ float g_q2[BATCH * NQ];
// approx partial keys: [b][q][chunk][slice][TSEL] u64 -> 67 MB
__device__ unsigned long long g_part[(size_t)BATCH * NQ * RCHUNKS * NSLICE * TSEL];

// ---------------------------------------------------------------------------
// Kernel 1: squared norms (bit-exact XLA-style warp tree; validated)
// ---------------------------------------------------------------------------
__global__ void norms_kernel(const float* __restrict__ ref,
                             const float* __restrict__ query) {
    int warp = (blockIdx.x * blockDim.x + threadIdx.x) >> 5;
    int lane = threadIdx.x & 31;
    int total = BATCH * NR + BATCH * NQ;
    if (warp >= total) return;

    const float* row;
    float* out;
    if (warp < BATCH * NR) {
        row = ref + (size_t)warp * DIM;
        out = g_r2 + warp;
    } else {
        int u = warp - BATCH * NR;
        row = query + (size_t)u * DIM;
        out = g_q2 + u;
    }

    float x0 = row[lane];
    float x1 = row[lane + 32];
    float s = __fadd_rn(__fmul_rn(x0, x0), __fmul_rn(x1, x1));
#pragma unroll
    for (int off = 16; off; off >>= 1)
        s = __fadd_rn(s, __shfl_down_sync(FULLM, s, off));
    if (lane == 0) *out = s;
}

// ---------------------------------------------------------------------------
// mma.sync m16n8k16 bf16 (A row-major, B col-major, fp32 accum) — validated
// ---------------------------------------------------------------------------
__device__ __forceinline__ void mma_bf16(float c[4],
                                         const uint32_t a[4],
                                         uint32_t b0, uint32_t b1) {
    asm volatile(
        "mma.sync.aligned.m16n8k16.row.col.f32.bf16.bf16.f32 "
        "{%0,%1,%2,%3}, {%4,%5,%6,%7}, {%8,%9}, {%0,%1,%2,%3};"
        : "+f"(c[0]), "+f"(c[1]), "+f"(c[2]), "+f"(c[3])
        : "r"(a[0]), "r"(a[1]), "r"(a[2]), "r"(a[3]), "r"(b0), "r"(b1));
}

// Branch-free sorted insert into ascending top-TSEL (dist,idx) lists.
__device__ __forceinline__ void insert8(float* dl, int* il, float dz, int iz) {
    if (dz < dl[TSEL - 1]) {
#pragma unroll
        for (int j = TSEL - 1; j >= 1; j--) {
            bool pA = dz < dl[j - 1];
            bool pB = dz < dl[j];
            il[j] = pA ? il[j - 1] : (pB ? iz : il[j]);
            dl[j] = pA ? dl[j - 1] : (pB ? dz : dl[j]);
        }
        bool p0 = dz < dl[0];
        il[0] = p0 ? iz : il[0];
        dl[0] = p0 ? dz : dl[0];
    }
}

// ---------------------------------------------------------------------------
// Kernel 2 (FUSED): 512 threads, 16 warps (8 m-groups x 2 n-halves).
// Per 128q x 1024r chunk, 8 r-tiles; HMMA candidate pass; selection directly
// on register fragments into per-(thread,qrow) top-8 lists. No d2 smem tile.
// ---------------------------------------------------------------------------
__global__ __launch_bounds__(512, 1) void fused_kernel(const float* __restrict__ ref,
                                                       const float* __restrict__ query) {
    extern __shared__ char smraw[];
    uint16_t* Qh  = (uint16_t*)smraw;                        // [TQ][QHS]
    uint16_t* Rh  = (uint16_t*)(smraw + TQ * QHS * 2);       // [TR][RHS]
    float*    r2s = (float*)(smraw + TQ * QHS * 2 + TR * RHS * 2); // [RCHUNK]

    int b   = blockIdx.z;
    int q0  = blockIdx.y * TQ;
    int cnk = blockIdx.x;
    int rbase = cnk * RCHUNK;
    int tid = threadIdx.x;

    int frow = tid >> 4;          // 0..31
    int fd   = (tid & 15) * 4;

    // Q tile -> bf16 smem
    const float* qg = query + ((size_t)b * NQ + q0) * DIM;
#pragma unroll
    for (int it = 0; it < 4; ++it) {
        int row = frow + it * 32;
        float4 v = *(const float4*)(qg + (size_t)row * DIM + fd);
        __nv_bfloat162 p0 = __floats2bfloat162_rn(v.x, v.y);
        __nv_bfloat162 p1 = __floats2bfloat162_rn(v.z, v.w);
        uint2 u;
        u.x = *(uint32_t*)&p0;
        u.y = *(uint32_t*)&p1;
        *(uint2*)&Qh[row * QHS + fd] = u;
    }
    // stage r2 chunk (1024 floats, float2 per thread)
    {
        float2 v = *(const float2*)(g_r2 + b * NR + rbase + tid * 2);
        *(float2*)(r2s + tid * 2) = v;
    }

    int warp = tid >> 5;
    int lane = tid & 31;
    int g  = lane >> 2;
    int t2 = (lane & 3) * 2;
    int wq = (warp >> 1) * 16;    // m-group base (8 groups)
    int wr = (warp & 1) * 64;     // n-half base

    float q2a = g_q2[b * NQ + q0 + wq + g];
    float q2b = g_q2[b * NQ + q0 + wq + g + 8];

    float dl0[TSEL], dl1[TSEL];
    int   il0[TSEL], il1[TSEL];
#pragma unroll
    for (int j = 0; j < TSEL; j++) {
        dl0[j] = INF_F; dl1[j] = INF_F; il0[j] = 0; il1[j] = 0;
    }

    for (int t = 0; t < RTILES; t++) {
        int r0 = rbase + t * TR;
        const float* rg = ref + ((size_t)b * NR + r0) * DIM;

        // R tile -> bf16 smem
#pragma unroll
        for (int it = 0; it < 4; ++it) {
            int row = frow + it * 32;
            float4 v = *(const float4*)(rg + (size_t)row * DIM + fd);
            __nv_bfloat162 p0 = __floats2bfloat162_rn(v.x, v.y);
            __nv_bfloat162 p1 = __floats2bfloat162_rn(v.z, v.w);
            uint2 u;
            u.x = *(uint32_t*)&p0;
            u.y = *(uint32_t*)&p1;
            *(uint2*)&Rh[row * RHS + fd] = u;
        }
        __syncthreads();   // tiles ready

        float c[8][4];
#pragma unroll
        for (int nt = 0; nt < 8; nt++)
#pragma unroll
            for (int e = 0; e < 4; e++) c[nt][e] = 0.f;

#pragma unroll
        for (int ks = 0; ks < 4; ks++) {
            int k0 = ks * 16;
            uint32_t a[4];
            const uint16_t* ap = &Qh[(wq + g) * QHS + k0 + t2];
            a[0] = *(const uint32_t*)ap;
            a[1] = *(const uint32_t*)(ap + 8 * QHS);
            a[2] = *(const uint32_t*)(ap + 8);
            a[3] = *(const uint32_t*)(ap + 8 * QHS + 8);
#pragma unroll
            for (int nt = 0; nt < 8; nt++) {
                const uint16_t* bp = &Rh[(wr + nt * 8 + g) * RHS + k0 + t2];
                uint32_t b0 = *(const uint32_t*)bp;
                uint32_t b1 = *(const uint32_t*)(bp + 8);
                mma_bf16(c[nt], a, b0, b1);
            }
        }

        // epilogue + in-register selection (approx pass)
#pragma unroll
        for (int nt = 0; nt < 8; nt++) {
            int rc = t * TR + wr + nt * 8 + t2;   // chunk-local ref col
            float rA = r2s[rc];
            float rB = r2s[rc + 1];
            int iA = r0 + wr + nt * 8 + t2;
            int iB = iA + 1;
            float d0 = fmaxf(__fmaf_rn(-2.f, c[nt][0], __fadd_rn(q2a, rA)), 0.f);
            float d1 = fmaxf(__fmaf_rn(-2.f, c[nt][1], __fadd_rn(q2a, rB)), 0.f);
            float d2_ = fmaxf(__fmaf_rn(-2.f, c[nt][2], __fadd_rn(q2b, rA)), 0.f);
            float d3 = fmaxf(__fmaf_rn(-2.f, c[nt][3], __fadd_rn(q2b, rB)), 0.f);
            insert8(dl0, il0, d0, iA);
            insert8(dl0, il0, d1, iB);
            insert8(dl1, il1, d2_, iA);
            insert8(dl1, il1, d3, iB);
        }
        __syncthreads();   // all reads of Rh done before next overwrite
    }

    // write partial lists: slice = n-half*4 + lane%4
    int slice = (warp & 1) * 4 + (lane & 3);
    {
        int q = q0 + wq + g;
        unsigned long long* dst = g_part +
            ((((size_t)(b * NQ + q)) * RCHUNKS + cnk) * NSLICE + slice) * TSEL;
#pragma unroll
        for (int j = 0; j < TSEL; j++)
            dst[j] = ((unsigned long long)__float_as_uint(dl0[j]) << 32) |
                     (unsigned)il0[j];
    }
    {
        int q = q0 + wq + g + 8;
        unsigned long long* dst = g_part +
            ((((size_t)(b * NQ + q)) * RCHUNKS + cnk) * NSLICE + slice) * TSEL;
#pragma unroll
        for (int j = 0; j < TSEL; j++)
            dst[j] = ((unsigned long long)__float_as_uint(dl1[j]) << 32) |
                     (unsigned)il1[j];
    }
}

// ---------------------------------------------------------------------------
// Kernel 3: merge 1024 approx keys/query -> approx top-32 -> EXACT rescore
// (validated sequential-k FMA chain + exact epilogue) -> exact top-16 out.
// Warp per query.
// ---------------------------------------------------------------------------
__global__ __launch_bounds__(256) void merge_kernel(const float* __restrict__ ref,
                                                    const float* __restrict__ query,
                                                    float* __restrict__ outD,
                                                    float* __restrict__ outI) {
    __shared__ float qs[8][DIM];

    int gwarp = (blockIdx.x * 256 + threadIdx.x) >> 5;
    int w     = (threadIdx.x >> 5) & 7;
    int lane  = threadIdx.x & 31;
    int b = gwarp / NQ;
    int q = gwarp % NQ;

    const float* qrow = query + ((size_t)b * NQ + q) * DIM;
    {
        float2 v = *(const float2*)(qrow + lane * 2);
        qs[w][lane * 2 + 0] = v.x;
        qs[w][lane * 2 + 1] = v.y;
    }
    __syncwarp();

    // gather 1024 approx keys -> per-lane sorted top-16 (u64 total order)
    const unsigned long long* src =
        g_part + (size_t)gwarp * RCHUNKS * NSLICE * TSEL;
    unsigned long long key[KNN];
#pragma unroll
    for (int j = 0; j < KNN; j++) key[j] = ~0ull;
#pragma unroll 8
    for (int i = 0; i < 32; i++) {
        unsigned long long kk = src[i * 32 + lane];
        if (kk < key[KNN - 1]) {
#pragma unroll
            for (int j = 0; j < KNN; j++) {
                if (kk < key[j]) {
                    unsigned long long tt = key[j]; key[j] = kk; kk = tt;
                }
            }
        }
    }

    // extract approx top-32; candidate r lands in lane r
    unsigned long long cand = ~0ull;
    for (int r = 0; r < NCAND; r++) {
        unsigned long long m = key[0];
#pragma unroll
        for (int off = 16; off; off >>= 1) {
            unsigned long long o = __shfl_xor_sync(FULLM, m, off);
            if (o < m) m = o;
        }
        if (key[0] == m) {   // unique winner pops
#pragma unroll
            for (int j = 0; j < KNN - 1; j++) key[j] = key[j + 1];
            key[KNN - 1] = ~0ull;
        }
        if (lane == r) cand = m;
    }
    int cidx = (int)(unsigned)(cand & 0xffffffffull);

    // exact rescore (bit-identical to validated pipeline)
    const float* rrow = ref + ((size_t)b * NR + cidx) * DIM;
    float dot = 0.f;
#pragma unroll
    for (int k4 = 0; k4 < DIM / 4; k4++) {
        float4 rv = *(const float4*)(rrow + k4 * 4);
        dot = __fmaf_rn(qs[w][k4 * 4 + 0], rv.x, dot);
        dot = __fmaf_rn(qs[w][k4 * 4 + 1], rv.y, dot);
        dot = __fmaf_rn(qs[w][k4 * 4 + 2], rv.z, dot);
        dot = __fmaf_rn(qs[w][k4 * 4 + 3], rv.w, dot);
    }
    float q2v = g_q2[b * NQ + q];
    float r2v = g_r2[b * NR + cidx];
    float d2 = fmaxf(__fmaf_rn(-2.f, dot, __fadd_rn(q2v, r2v)), 0.f);
    unsigned long long ekey =
        ((unsigned long long)__float_as_uint(d2) << 32) | (unsigned)cidx;

    float* Do = outD + (size_t)gwarp * KNN;
    float* Io = outI + (size_t)gwarp * KNN;

    for (int k = 0; k < KNN; k++) {
        unsigned long long m = ekey;
#pragma unroll
        for (int off = 16; off; off >>= 1) {
            unsigned long long o = __shfl_xor_sync(FULLM, m, off);
            if (o < m) m = o;
        }
        if (ekey == m) ekey = ~0ull;   // winner retires
        if (lane == 0) {
            Do[k] = sqrtf(__uint_as_float((unsigned)(m >> 32)));
            Io[k] = (float)(unsigned)(m & 0xffffffffull);
        }
    }
}

// ---------------------------------------------------------------------------
extern "C" void kernel_launch(void* const* d_in, const int* in_sizes, int n_in,
                              void* d_out, int out_size) {
    const float* ref   = (const float*)d_in[0];   // [B, NR, DIM]
    const float* query = (const float*)d_in[1];   // [B, NQ, DIM]

    float* outD = (float*)d_out;
    float* outI = outD + (size_t)BATCH * NQ * KNN;

    static const int smem_bytes = TQ * QHS * 2 + TR * RHS * 2 + RCHUNK * 4; // 40960
    cudaFuncSetAttribute(fused_kernel,
                         cudaFuncAttributeMaxDynamicSharedMemorySize, smem_bytes);

    int n_rows = BATCH * NR + BATCH * NQ;
    int n_thr  = n_rows * 32;
    norms_kernel<<<(n_thr + 255) / 256, 256>>>(ref, query);

    dim3 g(RCHUNKS, NQ / TQ, BATCH);   // (16, 16, 4) = 1024 blocks
    fused_kernel<<<g, 512, smem_bytes>>>(ref, query);

    merge_kernel<<<(BATCH * NQ * 32) / 256, 256>>>(ref, query, outD, outI);
}

// round 14
// speedup vs baseline: 2.9320x; 1.0570x over previous
#include <cuda_runtime.h>
#include <cuda_bf16.h>
#include <math.h>
#include <stdint.h>

#define BATCH 4
#define NQ    2048
#define NR    16384
#define DIM   64
#define KNN   16

#define TQ 128
#define TR 128
#define QHS 72            // bf16 row stride (64 + 8 pad) = 144 B, conflict-free
#define RHS 72

#define RCHUNKS 16
#define RCHUNK  (NR / RCHUNKS)      // 1024 refs per block
#define RTILES  (RCHUNK / TR)       // 8 tiles
#define TSEL  8                      // per-(thread,qrow) approx top-T
#define NSLICE 8                     // slices per (query, chunk)
#define NCAND 32                     // approx candidates rescored exactly

#define FULLM 0xffffffffu
#define INF_F __int_as_float(0x7f800000)

// Scratch (allocation-free rule: __device__ globals)
__device__ float g_r2[BATCH * NR];
__device__ float g_q2[BATCH * NQ];
// approx partial keys: [b][q][chunk][slice][TSEL] u64 -> 67 MB
__device__ unsigned long long g_part[(size_t)BATCH * NQ * RCHUNKS * NSLICE * TSEL];

// ---------------------------------------------------------------------------
// Kernel 1: squared norms (bit-exact XLA-style warp tree; validated)
// ---------------------------------------------------------------------------
__global__ void norms_kernel(const float* __restrict__ ref,
                             const float* __restrict__ query) {
    int warp = (blockIdx.x * blockDim.x + threadIdx.x) >> 5;
    int lane = threadIdx.x & 31;
    int total = BATCH * NR + BATCH * NQ;
    if (warp >= total) return;

    const float* row;
    float* out;
    if (warp < BATCH * NR) {
        row = ref + (size_t)warp * DIM;
        out = g_r2 + warp;
    } else {
        int u = warp - BATCH * NR;
        row = query + (size_t)u * DIM;
        out = g_q2 + u;
    }

    float x0 = row[lane];
    float x1 = row[lane + 32];
    float s = __fadd_rn(__fmul_rn(x0, x0), __fmul_rn(x1, x1));
#pragma unroll
    for (int off = 16; off; off >>= 1)
        s = __fadd_rn(s, __shfl_down_sync(FULLM, s, off));
    if (lane == 0) *out = s;
}

// ---------------------------------------------------------------------------
// mma.sync m16n8k16 bf16 (A row-major, B col-major, fp32 accum) — validated
// ---------------------------------------------------------------------------
__device__ __forceinline__ void mma_bf16(float c[4],
                                         const uint32_t a[4],
                                         uint32_t b0, uint32_t b1) {
    asm volatile(
        "mma.sync.aligned.m16n8k16.row.col.f32.bf16.bf16.f32 "
        "{%0,%1,%2,%3}, {%4,%5,%6,%7}, {%8,%9}, {%0,%1,%2,%3};"
        : "+f"(c[0]), "+f"(c[1]), "+f"(c[2]), "+f"(c[3])
        : "r"(a[0]), "r"(a[1]), "r"(a[2]), "r"(a[3]), "r"(b0), "r"(b1));
}

__device__ __forceinline__ void ldsm_x4(uint32_t r[4], uint32_t saddr) {
    asm volatile(
        "ldmatrix.sync.aligned.m8n8.x4.shared.b16 {%0,%1,%2,%3}, [%4];"
        : "=r"(r[0]), "=r"(r[1]), "=r"(r[2]), "=r"(r[3]) : "r"(saddr));
}

// Branch-free sorted insert into ascending top-TSEL (val,idx) lists.
__device__ __forceinline__ void insert8(float* dl, int* il, float dz, int iz) {
    if (dz < dl[TSEL - 1]) {
#pragma unroll
        for (int j = TSEL - 1; j >= 1; j--) {
            bool pA = dz < dl[j - 1];
            bool pB = dz < dl[j];
            il[j] = pA ? il[j - 1] : (pB ? iz : il[j]);
            dl[j] = pA ? dl[j - 1] : (pB ? dz : dl[j]);
        }
        bool p0 = dz < dl[0];
        il[0] = p0 ? iz : il[0];
        dl[0] = p0 ? dz : dl[0];
    }
}

// monotonic float -> u32 (total order incl. negatives)
__device__ __forceinline__ unsigned fmono(float f) {
    unsigned u = __float_as_uint(f);
    return u ^ (((unsigned)((int)u >> 31)) | 0x80000000u);
}

// ---------------------------------------------------------------------------
// Kernel 2 (FUSED): 512 threads, 16 warps (8 m-groups x 2 n-halves).
// HMMA candidate pass with ldmatrix fragments, double-buffered R tile with
// register prefetch, selection on v = r2 - 2*dot directly from fragments.
// ---------------------------------------------------------------------------
__global__ __launch_bounds__(512, 1) void fused_kernel(const float* __restrict__ ref,
                                                       const float* __restrict__ query) {
    extern __shared__ char smraw[];
    uint16_t* Qh  = (uint16_t*)smraw;                              // [TQ][QHS]
    uint16_t* Rh  = (uint16_t*)(smraw + TQ * QHS * 2);             // 2x [TR][RHS]
    float*    r2s = (float*)(smraw + TQ * QHS * 2 + 2 * TR * RHS * 2); // [RCHUNK]

    int b   = blockIdx.z;
    int q0  = blockIdx.y * TQ;
    int cnk = blockIdx.x;
    int rbase = cnk * RCHUNK;
    int tid = threadIdx.x;

    int frow = tid >> 4;          // 0..31
    int fd   = (tid & 15) * 4;

    // Q tile -> bf16 smem
    const float* qg = query + ((size_t)b * NQ + q0) * DIM;
#pragma unroll
    for (int it = 0; it < 4; ++it) {
        int row = frow + it * 32;
        float4 v = *(const float4*)(qg + (size_t)row * DIM + fd);
        __nv_bfloat162 p0 = __floats2bfloat162_rn(v.x, v.y);
        __nv_bfloat162 p1 = __floats2bfloat162_rn(v.z, v.w);
        uint2 u;
        u.x = *(uint32_t*)&p0;
        u.y = *(uint32_t*)&p1;
        *(uint2*)&Qh[row * QHS + fd] = u;
    }
    // stage r2 chunk
    {
        float2 v = *(const float2*)(g_r2 + b * NR + rbase + tid * 2);
        *(float2*)(r2s + tid * 2) = v;
    }

    // preload tile 0 into Rh buffer 0
    {
        const float* rg = ref + ((size_t)b * NR + rbase) * DIM;
#pragma unroll
        for (int it = 0; it < 4; ++it) {
            int row = frow + it * 32;
            float4 v = *(const float4*)(rg + (size_t)row * DIM + fd);
            __nv_bfloat162 p0 = __floats2bfloat162_rn(v.x, v.y);
            __nv_bfloat162 p1 = __floats2bfloat162_rn(v.z, v.w);
            uint2 u;
            u.x = *(uint32_t*)&p0;
            u.y = *(uint32_t*)&p1;
            *(uint2*)&Rh[row * RHS + fd] = u;
        }
    }
    __syncthreads();

    int warp = tid >> 5;
    int lane = tid & 31;
    int g  = lane >> 2;
    int t2 = (lane & 3) * 2;
    int wq = (warp >> 1) * 16;    // m-group base (8 groups)
    int wr = (warp & 1) * 64;     // n-half base

    // ldmatrix shared addresses (element offsets; *2 for bytes at use)
    // A: lanes 0-15 -> rows wq+(lane&15) klo; 16-31 -> same rows khi
    uint32_t qh_base = (uint32_t)__cvta_generic_to_shared(Qh);
    uint32_t rh_base = (uint32_t)__cvta_generic_to_shared(Rh);
    uint32_t a_addr0 = qh_base +
        (((wq + (lane & 15)) * QHS + (lane >> 4) * 8) << 1);
    // B: sel = lane>>3: nt-pair-half (sel>>1), k-half (sel&1)
    int sel = lane >> 3;
    uint32_t b_off0 = (((wr + (sel >> 1) * 8 + (lane & 7)) * RHS
                        + (sel & 1) * 8) << 1);

    float q2a = g_q2[b * NQ + q0 + wq + g];   // exact q2 kept for merge parity? (unused in select)
    (void)q2a;

    float dl0[TSEL], dl1[TSEL];
    int   il0[TSEL], il1[TSEL];
#pragma unroll
    for (int j = 0; j < TSEL; j++) {
        dl0[j] = INF_F; dl1[j] = INF_F; il0[j] = 0; il1[j] = 0;
    }

    for (int t = 0; t < RTILES; t++) {
        int r0 = rbase + t * TR;
        uint32_t cur = rh_base + (uint32_t)((t & 1) * TR * RHS * 2);
        uint16_t* nxt = Rh + ((t + 1) & 1) * TR * RHS;

        // prefetch next tile (LDG only; consumed after MMA)
        float4 pre[4];
        if (t < RTILES - 1) {
            const float* rg = ref + ((size_t)b * NR + r0 + TR) * DIM;
#pragma unroll
            for (int it = 0; it < 4; ++it)
                pre[it] = *(const float4*)(rg + (size_t)(frow + it * 32) * DIM + fd);
        }

        float c[8][4];
#pragma unroll
        for (int nt = 0; nt < 8; nt++)
#pragma unroll
            for (int e = 0; e < 4; e++) c[nt][e] = 0.f;

#pragma unroll
        for (int ks = 0; ks < 4; ks++) {
            uint32_t a[4];
            ldsm_x4(a, a_addr0 + (ks * 16 << 1));
#pragma unroll
            for (int p = 0; p < 4; p++) {
                uint32_t bb[4];
                ldsm_x4(bb, cur + b_off0
                            + (uint32_t)(((p * 16 * RHS) + ks * 16) << 1));
                mma_bf16(c[2 * p],     a, bb[0], bb[1]);
                mma_bf16(c[2 * p + 1], a, bb[2], bb[3]);
            }
        }

        // epilogue + in-register selection on v = r2 - 2*dot (order == d2)
#pragma unroll
        for (int nt = 0; nt < 8; nt++) {
            int rc = t * TR + wr + nt * 8 + t2;
            float rA = r2s[rc];
            float rB = r2s[rc + 1];
            int iA = r0 + wr + nt * 8 + t2;
            int iB = iA + 1;
            float v0 = __fmaf_rn(-2.f, c[nt][0], rA);
            float v1 = __fmaf_rn(-2.f, c[nt][1], rB);
            float v2 = __fmaf_rn(-2.f, c[nt][2], rA);
            float v3 = __fmaf_rn(-2.f, c[nt][3], rB);
            insert8(dl0, il0, v0, iA);
            insert8(dl0, il0, v1, iB);
            insert8(dl1, il1, v2, iA);
            insert8(dl1, il1, v3, iB);
        }

        // convert + store prefetched tile into alternate buffer
        if (t < RTILES - 1) {
#pragma unroll
            for (int it = 0; it < 4; ++it) {
                int row = frow + it * 32;
                __nv_bfloat162 p0 = __floats2bfloat162_rn(pre[it].x, pre[it].y);
                __nv_bfloat162 p1 = __floats2bfloat162_rn(pre[it].z, pre[it].w);
                uint2 u;
                u.x = *(uint32_t*)&p0;
                u.y = *(uint32_t*)&p1;
                *(uint2*)&nxt[row * RHS + fd] = u;
            }
        }
        __syncthreads();   // STS visible; all ldmatrix of cur done
    }

    // write partial lists: slice = n-half*4 + lane%4, keys = mono(v)<<32 | idx
    int slice = (warp & 1) * 4 + (lane & 3);
    {
        int q = q0 + wq + g;
        unsigned long long* dst = g_part +
            ((((size_t)(b * NQ + q)) * RCHUNKS + cnk) * NSLICE + slice) * TSEL;
#pragma unroll
        for (int j = 0; j < TSEL; j++)
            dst[j] = ((unsigned long long)fmono(dl0[j]) << 32) | (unsigned)il0[j];
    }
    {
        int q = q0 + wq + g + 8;
        unsigned long long* dst = g_part +
            ((((size_t)(b * NQ + q)) * RCHUNKS + cnk) * NSLICE + slice) * TSEL;
#pragma unroll
        for (int j = 0; j < TSEL; j++)
            dst[j] = ((unsigned long long)fmono(dl1[j]) << 32) | (unsigned)il1[j];
    }
}

// ---------------------------------------------------------------------------
// Kernel 3: merge 1024 approx keys/query -> approx top-32 -> EXACT rescore
// (validated sequential-k FMA chain + exact epilogue) -> exact top-16 out.
// Warp per query.
// ---------------------------------------------------------------------------
__global__ __launch_bounds__(256) void merge_kernel(const float* __restrict__ ref,
                                                    const float* __restrict__ query,
                                                    float* __restrict__ outD,
                                                    float* __restrict__ outI) {
    __shared__ float qs[8][DIM];

    int gwarp = (blockIdx.x * 256 + threadIdx.x) >> 5;
    int w     = (threadIdx.x >> 5) & 7;
    int lane  = threadIdx.x & 31;
    int b = gwarp / NQ;
    int q = gwarp % NQ;

    const float* qrow = query + ((size_t)b * NQ + q) * DIM;
    {
        float2 v = *(const float2*)(qrow + lane * 2);
        qs[w][lane * 2 + 0] = v.x;
        qs[w][lane * 2 + 1] = v.y;
    }
    __syncwarp();

    // gather 1024 approx keys -> per-lane sorted top-16 (u64 total order)
    const unsigned long long* src =
        g_part + (size_t)gwarp * RCHUNKS * NSLICE * TSEL;
    unsigned long long key[KNN];
#pragma unroll
    for (int j = 0; j < KNN; j++) key[j] = ~0ull;
#pragma unroll 8
    for (int i = 0; i < 32; i++) {
        unsigned long long kk = src[i * 32 + lane];
        if (kk < key[KNN - 1]) {
#pragma unroll
            for (int j = 0; j < KNN; j++) {
                if (kk < key[j]) {
                    unsigned long long tt = key[j]; key[j] = kk; kk = tt;
                }
            }
        }
    }

    // extract approx top-32; candidate r lands in lane r
    unsigned long long cand = ~0ull;
    for (int r = 0; r < NCAND; r++) {
        unsigned long long m = key[0];
#pragma unroll
        for (int off = 16; off; off >>= 1) {
            unsigned long long o = __shfl_xor_sync(FULLM, m, off);
            if (o < m) m = o;
        }
        if (key[0] == m) {   // unique winner pops
#pragma unroll
            for (int j = 0; j < KNN - 1; j++) key[j] = key[j + 1];
            key[KNN - 1] = ~0ull;
        }
        if (lane == r) cand = m;
    }
    int cidx = (int)(unsigned)(cand & 0xffffffffull);

    // exact rescore (bit-identical to validated pipeline)
    const float* rrow = ref + ((size_t)b * NR + cidx) * DIM;
    float dot = 0.f;
#pragma unroll
    for (int k4 = 0; k4 < DIM / 4; k4++) {
        float4 rv = *(const float4*)(rrow + k4 * 4);
        dot = __fmaf_rn(qs[w][k4 * 4 + 0], rv.x, dot);
        dot = __fmaf_rn(qs[w][k4 * 4 + 1], rv.y, dot);
        dot = __fmaf_rn(qs[w][k4 * 4 + 2], rv.z, dot);
        dot = __fmaf_rn(qs[w][k4 * 4 + 3], rv.w, dot);
    }
    float q2v = g_q2[b * NQ + q];
    float r2v = g_r2[b * NR + cidx];
    float d2 = fmaxf(__fmaf_rn(-2.f, dot, __fadd_rn(q2v, r2v)), 0.f);
    unsigned long long ekey =
        ((unsigned long long)__float_as_uint(d2) << 32) | (unsigned)cidx;

    float* Do = outD + (size_t)gwarp * KNN;
    float* Io = outI + (size_t)gwarp * KNN;

    for (int k = 0; k < KNN; k++) {
        unsigned long long m = ekey;
#pragma unroll
        for (int off = 16; off; off >>= 1) {
            unsigned long long o = __shfl_xor_sync(FULLM, m, off);
            if (o < m) m = o;
        }
        if (ekey == m) ekey = ~0ull;   // winner retires
        if (lane == 0) {
            Do[k] = sqrtf(__uint_as_float((unsigned)(m >> 32)));
            Io[k] = (float)(unsigned)(m & 0xffffffffull);
        }
    }
}

// ---------------------------------------------------------------------------
extern "C" void kernel_launch(void* const* d_in, const int* in_sizes, int n_in,
                              void* d_out, int out_size) {
    const float* ref   = (const float*)d_in[0];   // [B, NR, DIM]
    const float* query = (const float*)d_in[1];   // [B, NQ, DIM]

    float* outD = (float*)d_out;
    float* outI = outD + (size_t)BATCH * NQ * KNN;

    static const int smem_bytes =
        TQ * QHS * 2 + 2 * TR * RHS * 2 + RCHUNK * 4;  // 59392
    cudaFuncSetAttribute(fused_kernel,
                         cudaFuncAttributeMaxDynamicSharedMemorySize, smem_bytes);

    int n_rows = BATCH * NR + BATCH * NQ;
    int n_thr  = n_rows * 32;
    norms_kernel<<<(n_thr + 255) / 256, 256>>>(ref, query);

    dim3 g(RCHUNKS, NQ / TQ, BATCH);   // (16, 16, 4) = 1024 blocks
    fused_kernel<<<g, 512, smem_bytes>>>(ref, query);

    merge_kernel<<<(BATCH * NQ * 32) / 256, 256>>>(ref, query, outD, outI);
}